// round 1
// baseline (speedup 1.0000x reference)
#include <cuda_runtime.h>
#include <cuda_bf16.h>

// ForwardWarp: bilinear forward splat.
//   out[n,c, h + floor(flo[n,1,h,w]) + dx, w + floor(flo[n,0,h,w]) + dy]
//      += img[n,c,h,w] * wx(dx) * wy(dy)
// with wx = {1-fx, fx}, wy = {1-fy, fy}; OOB taps dropped.
// Shapes fixed by the reference: N=4, C=3, H=1080, W=1920, fp32.

#define FW_N 4
#define FW_C 3
#define FW_H 1080
#define FW_W 1920
#define FW_HW (FW_H * FW_W)
#define FW_NPIX (FW_N * FW_HW)

__global__ __launch_bounds__(256) void forward_warp_kernel(
    const float* __restrict__ img,
    const float* __restrict__ flo,
    float* __restrict__ out)
{
    int p = blockIdx.x * blockDim.x + threadIdx.x;
    if (p >= FW_NPIX) return;

    int n  = p / FW_HW;
    int hw = p - n * FW_HW;
    int h  = hw / FW_W;
    int w  = hw - h * FW_W;

    // flo channel 0 -> column shift (y in reference), channel 1 -> row shift (x).
    const float* flo_n = flo + (size_t)n * 2 * FW_HW;
    float ycol = flo_n[hw];          // channel 0
    float xrow = flo_n[FW_HW + hw];  // channel 1

    float xf = floorf(xrow);
    float yf = floorf(ycol);
    int ix = (int)xf;
    int iy = (int)yf;
    float fx = xrow - xf;   // row fractional weight (pairs with dx)
    float fy = ycol - yf;   // col fractional weight (pairs with dy)

    const float* img_n = img + (size_t)n * FW_C * FW_HW;
    float c0 = img_n[hw];
    float c1 = img_n[FW_HW + hw];
    float c2 = img_n[2 * FW_HW + hw];

    float wx0 = 1.0f - fx, wx1 = fx;
    float wy0 = 1.0f - fy, wy1 = fy;

    int rbase = h + ix;
    int cbase = w + iy;

    float* out_n = out + (size_t)n * FW_C * FW_HW;

    #pragma unroll
    for (int dx = 0; dx < 2; dx++) {
        int rr = rbase + dx;
        if (rr < 0 || rr >= FW_H) continue;
        float wx = (dx == 0) ? wx0 : wx1;
        #pragma unroll
        for (int dy = 0; dy < 2; dy++) {
            int cc = cbase + dy;
            if (cc < 0 || cc >= FW_W) continue;
            float wgt = wx * ((dy == 0) ? wy0 : wy1);
            int o = rr * FW_W + cc;
            atomicAdd(out_n + o,               c0 * wgt);
            atomicAdd(out_n + FW_HW + o,       c1 * wgt);
            atomicAdd(out_n + 2 * FW_HW + o,   c2 * wgt);
        }
    }
}

extern "C" void kernel_launch(void* const* d_in, const int* in_sizes, int n_in,
                              void* d_out, int out_size)
{
    const float* img = (const float*)d_in[0];
    const float* flo = (const float*)d_in[1];
    float* out = (float*)d_out;

    // Output is poisoned; the scatter needs zeros. Memset node is graph-capturable.
    cudaMemsetAsync(out, 0, (size_t)out_size * sizeof(float), 0);

    int threads = 256;
    int blocks = (FW_NPIX + threads - 1) / threads;
    forward_warp_kernel<<<blocks, threads>>>(img, flo, out);
}

// round 2
// speedup vs baseline: 1.0151x; 1.0151x over previous
#include <cuda_runtime.h>
#include <cuda_bf16.h>

// ForwardWarp: bilinear forward splat, N=4, C=3, H=1080, W=1920, fp32.
// out[n,c, h+floor(flo[n,1,h,w])+dx, w+floor(flo[n,0,h,w])+dy]
//   += img[n,c,h,w] * wx(dx) * wy(dy);  OOB taps dropped.

#define FW_N 4
#define FW_C 3
#define FW_H 1080
#define FW_W 1920
#define FW_HW (FW_H * FW_W)

// Grid: (FW_W/128, FW_H, FW_N), block 128 -> w exact, no guards, no div/mod.
__global__ __launch_bounds__(128) void forward_warp_kernel(
    const float* __restrict__ img,
    const float* __restrict__ flo,
    float* __restrict__ out)
{
    const int w = blockIdx.x * 128 + threadIdx.x;   // < 1920 always
    const int h = blockIdx.y;
    const int n = blockIdx.z;
    const int hw = h * FW_W + w;

    // flo channel 0 -> column shift, channel 1 -> row shift.
    const float* flo_n = flo + (size_t)n * 2 * FW_HW;
    const float ycol = __ldcs(flo_n + hw);
    const float xrow = __ldcs(flo_n + FW_HW + hw);

    const float xf = floorf(xrow);
    const float yf = floorf(ycol);
    const int ix = (int)xf;
    const int iy = (int)yf;
    const float fx = xrow - xf;   // row fractional weight
    const float fy = ycol - yf;   // col fractional weight

    const float* img_n = img + (size_t)n * FW_C * FW_HW;
    const float c0 = __ldcs(img_n + hw);
    const float c1 = __ldcs(img_n + FW_HW + hw);
    const float c2 = __ldcs(img_n + 2 * FW_HW + hw);

    const float wx0 = 1.0f - fx;
    const float wy0 = 1.0f - fy;

    const int rbase = h + ix;
    const int cbase = w + iy;

    float* __restrict__ out_n = out + (size_t)n * FW_C * FW_HW;

    #pragma unroll
    for (int dx = 0; dx < 2; dx++) {
        const int rr = rbase + dx;
        if ((unsigned)rr >= (unsigned)FW_H) continue;
        const float wx = dx ? (fx) : (wx0);
        const int rowoff = rr * FW_W;
        #pragma unroll
        for (int dy = 0; dy < 2; dy++) {
            const int cc = cbase + dy;
            if ((unsigned)cc >= (unsigned)FW_W) continue;
            const float wgt = wx * (dy ? fy : wy0);
            float* p = out_n + (rowoff + cc);
            atomicAdd(p,               c0 * wgt);
            atomicAdd(p + FW_HW,       c1 * wgt);
            atomicAdd(p + 2 * FW_HW,   c2 * wgt);
        }
    }
}

extern "C" void kernel_launch(void* const* d_in, const int* in_sizes, int n_in,
                              void* d_out, int out_size)
{
    const float* img = (const float*)d_in[0];
    const float* flo = (const float*)d_in[1];
    float* out = (float*)d_out;

    cudaMemsetAsync(out, 0, (size_t)out_size * sizeof(float), 0);

    dim3 grid(FW_W / 128, FW_H, FW_N);
    forward_warp_kernel<<<grid, 128>>>(img, flo, out);
}

// round 3
// speedup vs baseline: 1.2807x; 1.2617x over previous
#include <cuda_runtime.h>
#include <cuda_bf16.h>
#include <cstdint>

// ForwardWarp, N=4, C=3, H=1080, W=1920, fp32.
// Strategy: splat into NHWC-pad4 scratch with one red.global.add.v4.f32 per
// bilinear tap (3 channels + pad in a single 16B atomic), then transpose
// scratch -> NCHW output. Cuts L1 atomic wavefronts ~3x vs planar scatter.

#define FW_N 4
#define FW_C 3
#define FW_H 1080
#define FW_W 1920
#define FW_HW (FW_H * FW_W)
#define FW_SCRATCH_ELEMS (FW_N * FW_HW * 4)   // 33,177,600 floats = 132.7 MB

__device__ float fw_scratch[FW_SCRATCH_ELEMS];

// ---------------- zero scratch (float4 stores, exact grid) ----------------
__global__ __launch_bounds__(1024) void fw_zero_kernel()
{
    // 8,294,400 float4 elements = 8100 blocks * 1024 threads exactly.
    size_t i = (size_t)blockIdx.x * 1024 + threadIdx.x;
    reinterpret_cast<float4*>(fw_scratch)[i] = make_float4(0.f, 0.f, 0.f, 0.f);
}

// ---------------- scatter ----------------
__device__ __forceinline__ void red_add_v4(float* p, float a, float b, float c, float d)
{
    asm volatile("red.global.add.v4.f32 [%0], {%1, %2, %3, %4};"
                 :: "l"(p), "f"(a), "f"(b), "f"(c), "f"(d) : "memory");
}

// Grid: (FW_W/128, FW_H, FW_N), block 128.
__global__ __launch_bounds__(128) void fw_scatter_kernel(
    const float* __restrict__ img,
    const float* __restrict__ flo)
{
    const int w = blockIdx.x * 128 + threadIdx.x;
    const int h = blockIdx.y;
    const int n = blockIdx.z;
    const int hw = h * FW_W + w;

    // flo channel 0 -> column shift, channel 1 -> row shift.
    const float* flo_n = flo + (size_t)n * 2 * FW_HW;
    const float ycol = __ldcs(flo_n + hw);
    const float xrow = __ldcs(flo_n + FW_HW + hw);

    const float xf = floorf(xrow);
    const float yf = floorf(ycol);
    const int ix = (int)xf;
    const int iy = (int)yf;
    const float fx = xrow - xf;   // row frac
    const float fy = ycol - yf;   // col frac

    const float* img_n = img + (size_t)n * FW_C * FW_HW;
    const float c0 = __ldcs(img_n + hw);
    const float c1 = __ldcs(img_n + FW_HW + hw);
    const float c2 = __ldcs(img_n + 2 * FW_HW + hw);

    const float wx0 = 1.0f - fx;
    const float wy0 = 1.0f - fy;

    const int rbase = h + ix;
    const int cbase = w + iy;

    float* __restrict__ sc_n = fw_scratch + (size_t)n * FW_HW * 4;

    #pragma unroll
    for (int dx = 0; dx < 2; dx++) {
        const int rr = rbase + dx;
        if ((unsigned)rr >= (unsigned)FW_H) continue;
        const float wx = dx ? fx : wx0;
        const int rowoff = rr * FW_W;
        #pragma unroll
        for (int dy = 0; dy < 2; dy++) {
            const int cc = cbase + dy;
            if ((unsigned)cc >= (unsigned)FW_W) continue;
            const float wgt = wx * (dy ? fy : wy0);
            float* p = sc_n + (size_t)(rowoff + cc) * 4;
            red_add_v4(p, c0 * wgt, c1 * wgt, c2 * wgt, 0.0f);
        }
    }
}

// ---------------- transpose NHWC-pad4 -> NCHW ----------------
// Grid: (FW_W/128, FW_H, FW_N), block 128.
__global__ __launch_bounds__(128) void fw_transpose_kernel(float* __restrict__ out)
{
    const int w = blockIdx.x * 128 + threadIdx.x;
    const int h = blockIdx.y;
    const int n = blockIdx.z;
    const int hw = h * FW_W + w;

    const float4 v = reinterpret_cast<const float4*>(fw_scratch)[(size_t)n * FW_HW + hw];

    float* __restrict__ out_n = out + (size_t)n * FW_C * FW_HW;
    out_n[hw]              = v.x;
    out_n[FW_HW + hw]      = v.y;
    out_n[2 * FW_HW + hw]  = v.z;
}

extern "C" void kernel_launch(void* const* d_in, const int* in_sizes, int n_in,
                              void* d_out, int out_size)
{
    const float* img = (const float*)d_in[0];
    const float* flo = (const float*)d_in[1];
    float* out = (float*)d_out;

    fw_zero_kernel<<<8100, 1024>>>();

    dim3 grid(FW_W / 128, FW_H, FW_N);
    fw_scatter_kernel<<<grid, 128>>>(img, flo);
    fw_transpose_kernel<<<grid, 128>>>(out);
}